// round 3
// baseline (speedup 1.0000x reference)
#include <cuda_runtime.h>
#include <cstdint>

// Problem constants
#define BATCH 8
#define C     192
#define CQ    32
#define NPIX  16384
#define SUB   64              // pixels per subtile (2 per thread)
#define NSUBT 4               // subtiles per block
#define TILE  (SUB*NSUBT)     // 256 pixels per block
#define NPARTS (NPIX/TILE)    // 64 blocks per batch
#define KC    32              // k-chunk for Wv staging

typedef unsigned long long u64;

// ---------------- deterministic scratch (no allocations, no atomics) ----------
__device__ float g_part_mat [BATCH*NPARTS*CQ*C];
__device__ float g_part_vsum[BATCH*NPARTS*C];
__device__ float g_part_ksum[BATCH*NPARTS*CQ];
__device__ float g_mat [BATCH*CQ*C];
__device__ float g_vsum[BATCH*C];
__device__ float g_ksum[BATCH*CQ];

// ---------------- packed f32x2 helpers ----------------
__device__ __forceinline__ u64 pack2dup(float x) {
    u64 r; asm("mov.b64 %0, {%1, %1};" : "=l"(r) : "f"(x)); return r;
}
__device__ __forceinline__ u64 pack2(float a, float b) {
    u64 r; asm("mov.b64 %0, {%1, %2};" : "=l"(r) : "f"(a), "f"(b)); return r;
}
__device__ __forceinline__ void unpack2(u64 v, float& lo, float& hi) {
    asm("mov.b64 {%0, %1}, %2;" : "=f"(lo), "=f"(hi) : "l"(v));
}
__device__ __forceinline__ u64 ffma2(u64 a, u64 b, u64 c) {
    u64 d; asm("fma.rn.f32x2 %0, %1, %2, %3;" : "=l"(d) : "l"(a), "l"(b), "l"(c));
    return d;
}
__device__ __forceinline__ u64 fmul2(u64 a, u64 b) {
    u64 d; asm("mul.rn.f32x2 %0, %1, %2;" : "=l"(d) : "l"(a), "l"(b)); return d;
}
__device__ __forceinline__ u64 fadd2(u64 a, u64 b) {
    u64 d; asm("add.rn.f32x2 %0, %1, %2;" : "=l"(d) : "l"(a), "l"(b)); return d;
}

// ---------------- smem layouts (float offsets) ----------------
// pass1
#define P1_BUF0   0       // xs [192][64] (12288) or vt [64][194] (12416)
#define P1_WV     12416   // [32][194] = 6208
#define P1_WK     18624   // [32][192] = 6144
#define P1_KN     24768   // [32][64]  = 2048
#define P1_KSQ    26816   // [8][64]   = 512
#define P1_INVN   27328   // [64]
#define P1_WKP    27392   // [32]
#define P1_KSUML  27424   // [32]
#define P1_VSUML  27456   // [192]
#define P1_TOT    27648
#define SMEM1_BYTES (P1_TOT*4)

// pass2
#define P2_XS     0       // [192][64] = 12288
#define P2_MATS   12288   // [32][192] = 6144
#define P2_QN     18432   // [32][64]  = 2048
#define P2_QSQ    20480   // [8][64]   = 512
#define P2_INVN   20992   // [64]
#define P2_SDP    21056   // [8][64]   = 512
#define P2_TS     21568   // [64]
#define P2_KSUM   21632   // [32]
#define P2_VSUM   21664   // [192]
#define P2_TOT    21856
#define SMEM2_BYTES (P2_TOT*4)

// =============================================================================
// Pass 1
// =============================================================================
__global__ __launch_bounds__(256, 2)
void pass1_kernel(const float* __restrict__ x, const float* __restrict__ x1,
                  const float* __restrict__ Wk, const float* __restrict__ bk,
                  const float* __restrict__ Wv, const float* __restrict__ bv)
{
    extern __shared__ float sm[];
    float* buf0  = sm + P1_BUF0;
    float* wv    = sm + P1_WV;
    float* wk    = sm + P1_WK;
    float* kn    = sm + P1_KN;
    float* ksq   = sm + P1_KSQ;
    float* invn  = sm + P1_INVN;
    float* wkp   = sm + P1_WKP;
    float* ksuml = sm + P1_KSUML;
    float* vsuml = sm + P1_VSUML;

    const int tid  = threadIdx.x;
    const int lane = tid & 31;
    const int wgrp = tid >> 5;
    const int b    = blockIdx.y;
    const int part = blockIdx.x;
    const int pl   = 2 * lane;       // pixel-pair base within subtile
    const int c0   = wgrp * 24;      // channel block for V

    // stage Wk once per block (row-major copy, coalesced + conflict-free)
#pragma unroll
    for (int i = 0; i < 24; i++) wk[tid + i * 256] = Wk[tid + i * 256];
    if (tid < 32)  ksuml[tid] = 0.f;
    if (tid < 192) vsuml[tid] = 0.f;

    // matrix accumulators: m = wgrp + 8*i, ch-pair = 2*lane + 64*j
    u64 macc[4][3];
#pragma unroll
    for (int i = 0; i < 4; i++)
#pragma unroll
        for (int j = 0; j < 3; j++) macc[i][j] = 0ull;

    const float* x1b = x1 + (size_t)b * C * NPIX;
    const float* xb  = x  + (size_t)b * C * NPIX;

    for (int s = 0; s < NSUBT; s++) {
        const int n0 = part * TILE + s * SUB;
        __syncthreads();   // protect buf0(vt)/kn from previous subtile readers

        // ---- load x1 subtile: buf0[c][t] (float2 per thread) ----
#pragma unroll
        for (int i = 0; i < 24; i++) {
            int c = wgrp + 8 * i;
            *(float2*)&buf0[c * 64 + pl] =
                *(const float2*)&x1b[(size_t)c * NPIX + n0 + pl];
        }
        __syncthreads();

        // ---- K projection (packed over pixel pair) ----
        u64 acc2[4];
#pragma unroll
        for (int u = 0; u < 4; u++) acc2[u] = pack2dup(bk[wgrp + 8 * u]);
#pragma unroll 8
        for (int k = 0; k < C; k++) {
            u64 xp = *(const u64*)&buf0[k * 64 + pl];
#pragma unroll
            for (int u = 0; u < 4; u++)
                acc2[u] = ffma2(xp, pack2dup(wk[(wgrp + 8 * u) * 192 + k]), acc2[u]);
        }
        // per-pixel sum of squares (packed)
        {
            u64 sq = fmul2(acc2[0], acc2[0]);
#pragma unroll
            for (int u = 1; u < 4; u++) sq = ffma2(acc2[u], acc2[u], sq);
            *(u64*)&ksq[wgrp * 64 + pl] = sq;
        }
        __syncthreads();
        if (tid < 64) {
            float tot = 0.f;
#pragma unroll
            for (int g = 0; g < 8; g++) tot += ksq[g * 64 + tid];
            invn[tid] = rsqrtf(tot);
        }
        __syncthreads();
        {
            u64 inv2 = *(const u64*)&invn[pl];
#pragma unroll
            for (int u = 0; u < 4; u++) {
                u64 kp = fmul2(acc2[u], inv2);
                *(u64*)&kn[(wgrp + 8 * u) * 64 + pl] = kp;
                float lo, hi; unpack2(kp, lo, hi);
                float sv = lo + hi;
#pragma unroll
                for (int off = 16; off; off >>= 1)
                    sv += __shfl_down_sync(0xffffffffu, sv, off);
                if (lane == 0) wkp[wgrp * 4 + u] = sv;
            }
        }
        __syncthreads();
        if (tid < 32) ksuml[tid] += wkp[(tid & 7) * 4 + (tid >> 3)];

        // ---- load x subtile (overwrite xs region) ----
        // (safe: all xs(x1) reads completed before the ksq __syncthreads)
#pragma unroll
        for (int i = 0; i < 24; i++) {
            int c = wgrp + 8 * i;
            *(float2*)&buf0[c * 64 + pl] =
                *(const float2*)&xb[(size_t)c * NPIX + n0 + pl];
        }

        // ---- V projection: 2 px x 12 ch-pairs per thread ----
        u64 vacc[2][12];
#pragma unroll
        for (int j = 0; j < 12; j++) {
            float2 bvv = *(const float2*)&bv[c0 + 2 * j];
            u64 bp = pack2(bvv.x, bvv.y);
            vacc[0][j] = bp; vacc[1][j] = bp;
        }
        for (int kc0 = 0; kc0 < C; kc0 += KC) {
            __syncthreads();   // prev wv chunk consumed; first iter: xs visible
#pragma unroll
            for (int i = 0; i < 24; i++) {
                int idx = tid + i * 256;
                int cc = idx >> 5, kk = idx & 31;
                wv[kk * 194 + cc] = Wv[(size_t)cc * C + kc0 + kk];
            }
            __syncthreads();
#pragma unroll 8
            for (int kk = 0; kk < KC; kk++) {
                float2 xv = *(const float2*)&buf0[(kc0 + kk) * 64 + pl];
                u64 x0 = pack2dup(xv.x);
                u64 x1d = pack2dup(xv.y);
#pragma unroll
                for (int j = 0; j < 12; j++) {
                    u64 w2 = *(const u64*)&wv[kk * 194 + c0 + 2 * j];
                    vacc[0][j] = ffma2(w2, x0, vacc[0][j]);
                    vacc[1][j] = ffma2(w2, x1d, vacc[1][j]);
                }
            }
        }
        __syncthreads();   // all xs reads done -> can overwrite with vt

        // ---- write V tile: vt[t][c] stride 194 (aliases xs region) ----
#pragma unroll
        for (int j = 0; j < 12; j++) {
            *(u64*)&buf0[(pl)     * 194 + c0 + 2 * j] = vacc[0][j];
            *(u64*)&buf0[(pl + 1) * 194 + c0 + 2 * j] = vacc[1][j];
        }
        __syncthreads();

        // ---- vsum (warps 0..2, packed, single owner per channel pair) ----
        if (tid < 96) {
            u64 sv = 0ull;
#pragma unroll 8
            for (int t = 0; t < SUB; t++)
                sv = fadd2(sv, *(const u64*)&buf0[t * 194 + 2 * tid]);
            float lo, hi; unpack2(sv, lo, hi);
            vsuml[2 * tid]     += lo;
            vsuml[2 * tid + 1] += hi;
        }

        // ---- matrix += Kn * V^T ----
#pragma unroll 2
        for (int t = 0; t < SUB; t++) {
            u64 kd[4];
#pragma unroll
            for (int i = 0; i < 4; i++)
                kd[i] = pack2dup(kn[(wgrp + 8 * i) * 64 + t]);
#pragma unroll
            for (int j = 0; j < 3; j++) {
                u64 v2 = *(const u64*)&buf0[t * 194 + pl + 64 * j];
#pragma unroll
                for (int i = 0; i < 4; i++)
                    macc[i][j] = ffma2(kd[i], v2, macc[i][j]);
            }
        }
    }

    __syncthreads();
    // ---- write per-block partials (deterministic) ----
    float* pm = g_part_mat + ((size_t)b * NPARTS + part) * CQ * C;
#pragma unroll
    for (int i = 0; i < 4; i++)
#pragma unroll
        for (int j = 0; j < 3; j++)
            *(u64*)&pm[(wgrp + 8 * i) * C + pl + 64 * j] = macc[i][j];
    if (tid < 192) g_part_vsum[((size_t)b * NPARTS + part) * C  + tid] = vsuml[tid];
    if (tid < 32)  g_part_ksum[((size_t)b * NPARTS + part) * CQ + tid] = ksuml[tid];
}

// =============================================================================
// Reduce partials (fixed order => deterministic)
// =============================================================================
__global__ void reduce_kernel()
{
    const int MATN = BATCH * CQ * C;
    const int VSN  = BATCH * C;
    const int KSN  = BATCH * CQ;
    int idx = blockIdx.x * blockDim.x + threadIdx.x;
    if (idx < MATN) {
        int bb = idx / (CQ * C), r = idx % (CQ * C);
        const float* p = g_part_mat + (size_t)bb * NPARTS * CQ * C + r;
        float sv = 0.f;
#pragma unroll 8
        for (int q = 0; q < NPARTS; q++) sv += p[(size_t)q * CQ * C];
        g_mat[idx] = sv;
    } else if (idx < MATN + VSN) {
        int k = idx - MATN;
        int bb = k / C, r = k % C;
        const float* p = g_part_vsum + (size_t)bb * NPARTS * C + r;
        float sv = 0.f;
#pragma unroll 8
        for (int q = 0; q < NPARTS; q++) sv += p[q * C];
        g_vsum[k] = sv;
    } else if (idx < MATN + VSN + KSN) {
        int k = idx - MATN - VSN;
        int bb = k / CQ, r = k % CQ;
        const float* p = g_part_ksum + (size_t)bb * NPARTS * CQ + r;
        float sv = 0.f;
#pragma unroll 8
        for (int q = 0; q < NPARTS; q++) sv += p[q * CQ];
        g_ksum[k] = sv;
    }
}

// =============================================================================
// Pass 2
// =============================================================================
__global__ __launch_bounds__(256, 2)
void pass2_kernel(const float* __restrict__ x1,
                  const float* __restrict__ Wq, const float* __restrict__ bq,
                  const float* __restrict__ gamma, float* __restrict__ out)
{
    extern __shared__ float sm[];
    float* xs     = sm + P2_XS;
    float* mats   = sm + P2_MATS;
    float* qn     = sm + P2_QN;
    float* qsq    = sm + P2_QSQ;
    float* invn   = sm + P2_INVN;
    float* sdp    = sm + P2_SDP;
    float* ts_s   = sm + P2_TS;
    float* ksum_s = sm + P2_KSUM;
    float* vsum_s = sm + P2_VSUM;

    const int tid  = threadIdx.x;
    const int lane = tid & 31;
    const int wgrp = tid >> 5;
    const int b    = blockIdx.y;
    const int part = blockIdx.x;
    const int pl   = 2 * lane;
    const int c0   = wgrp * 24;
    const float gm = gamma[0];

#pragma unroll
    for (int i = 0; i < 24; i++)
        mats[tid + i * 256] = g_mat[(size_t)b * CQ * C + tid + i * 256];
    if (tid < 32)  ksum_s[tid] = g_ksum[b * CQ + tid] + 1e-6f;
    if (tid < 192) vsum_s[tid] = g_vsum[b * C + tid];

    const float* x1b = x1 + (size_t)b * C * NPIX;
    float* outb = out + (size_t)b * C * NPIX;

    for (int s = 0; s < NSUBT; s++) {
        const int n0 = part * TILE + s * SUB;
        __syncthreads();
#pragma unroll
        for (int i = 0; i < 24; i++) {
            int c = wgrp + 8 * i;
            *(float2*)&xs[c * 64 + pl] =
                *(const float2*)&x1b[(size_t)c * NPIX + n0 + pl];
        }
        __syncthreads();

        // ---- Q projection (packed over pixel pair) ----
        u64 acc2[4];
#pragma unroll
        for (int u = 0; u < 4; u++) acc2[u] = pack2dup(bq[wgrp + 8 * u]);
        // Wq staged to mats? mats busy — read Wq through L1 here would regress;
        // instead stage Wq into qn region? qn needed. Use read-only global:
        // NOTE: stage Wq into a dedicated smem reuse of qsq/sdp is too small.
        // Wq is only 24KB of L2-resident data shared by all blocks; per-k loads
        // below are broadcast (lane-invariant) -> 4 LDG/k, L1-resident.
#pragma unroll 8
        for (int k = 0; k < C; k++) {
            u64 xp = *(const u64*)&xs[k * 64 + pl];
#pragma unroll
            for (int u = 0; u < 4; u++)
                acc2[u] = ffma2(xp, pack2dup(__ldg(&Wq[(wgrp + 8 * u) * C + k])), acc2[u]);
        }
        {
            u64 sq = fmul2(acc2[0], acc2[0]);
#pragma unroll
            for (int u = 1; u < 4; u++) sq = ffma2(acc2[u], acc2[u], sq);
            *(u64*)&qsq[wgrp * 64 + pl] = sq;
        }
        __syncthreads();
        if (tid < 64) {
            float tot = 0.f;
#pragma unroll
            for (int g = 0; g < 8; g++) tot += qsq[g * 64 + tid];
            invn[tid] = rsqrtf(tot);
        }
        __syncthreads();
        {
            u64 inv2 = *(const u64*)&invn[pl];
            u64 sd2 = 0ull;
#pragma unroll
            for (int u = 0; u < 4; u++) {
                u64 qp = fmul2(acc2[u], inv2);
                *(u64*)&qn[(wgrp + 8 * u) * 64 + pl] = qp;
                sd2 = ffma2(qp, pack2dup(ksum_s[wgrp + 8 * u]), sd2);
            }
            *(u64*)&sdp[wgrp * 64 + pl] = sd2;
        }
        __syncthreads();
        if (tid < 64) {
            float tot = 0.f;
#pragma unroll
            for (int g = 0; g < 8; g++) tot += sdp[g * 64 + tid];
            ts_s[tid] = 1.0f / (16384.0f + tot);
        }
        __syncthreads();

        // ---- out GEMM: 2 px x 12 ch-pairs per thread ----
        u64 oacc[2][12];
#pragma unroll
        for (int j = 0; j < 12; j++) {
            u64 vp = *(const u64*)&vsum_s[c0 + 2 * j];
            oacc[0][j] = vp; oacc[1][j] = vp;
        }
#pragma unroll 4
        for (int m = 0; m < CQ; m++) {
            float2 qq = *(const float2*)&qn[m * 64 + pl];
            u64 q0 = pack2dup(qq.x);
            u64 q1 = pack2dup(qq.y);
#pragma unroll
            for (int j = 0; j < 12; j++) {
                u64 w2 = *(const u64*)&mats[m * C + c0 + 2 * j];
                oacc[0][j] = ffma2(w2, q0, oacc[0][j]);
                oacc[1][j] = ffma2(w2, q1, oacc[1][j]);
            }
        }
        {
            float2 tss = *(const float2*)&ts_s[pl];
            u64 g0 = pack2dup(gm * tss.x);
            u64 g1 = pack2dup(gm * tss.y);
#pragma unroll
            for (int j = 0; j < 12; j++) {
                u64 o0 = fmul2(oacc[0][j], g0);
                u64 o1 = fmul2(oacc[1][j], g1);
                float a0, a1, b0, b1;
                unpack2(o0, a0, a1);
                unpack2(o1, b0, b1);
                // coalesced STG.64: {px0, px1} contiguous per channel
                *(float2*)&outb[(size_t)(c0 + 2 * j)     * NPIX + n0 + pl] =
                    make_float2(a0, b0);
                *(float2*)&outb[(size_t)(c0 + 2 * j + 1) * NPIX + n0 + pl] =
                    make_float2(a1, b1);
            }
        }
    }
}

// =============================================================================
extern "C" void kernel_launch(void* const* d_in, const int* in_sizes, int n_in,
                              void* d_out, int out_size)
{
    const float* x     = (const float*)d_in[0];
    const float* x1    = (const float*)d_in[1];
    const float* Wq    = (const float*)d_in[2];
    const float* bq    = (const float*)d_in[3];
    const float* Wk    = (const float*)d_in[4];
    const float* bk    = (const float*)d_in[5];
    const float* Wv    = (const float*)d_in[6];
    const float* bv    = (const float*)d_in[7];
    const float* gamma = (const float*)d_in[8];
    float* out = (float*)d_out;

    cudaFuncSetAttribute(pass1_kernel,
                         cudaFuncAttributeMaxDynamicSharedMemorySize, SMEM1_BYTES);
    cudaFuncSetAttribute(pass2_kernel,
                         cudaFuncAttributeMaxDynamicSharedMemorySize, SMEM2_BYTES);

    dim3 grid(NPARTS, BATCH);
    pass1_kernel<<<grid, 256, SMEM1_BYTES>>>(x, x1, Wk, bk, Wv, bv);

    const int RED = BATCH * CQ * C + BATCH * C + BATCH * CQ;
    reduce_kernel<<<(RED + 255) / 256, 256>>>();

    pass2_kernel<<<grid, 256, SMEM2_BYTES>>>(x1, Wq, bq, gamma, out);
}

// round 4
// speedup vs baseline: 2.2341x; 2.2341x over previous
#include <cuda_runtime.h>
#include <cstdint>

#define BATCH 8
#define C     192
#define CQ    32
#define NPIX  16384
#define SUB   64
#define NSUBT 4
#define TILE  (SUB*NSUBT)
#define NPARTS (NPIX/TILE)   // 64

typedef unsigned long long u64;

// ---------------- deterministic scratch ----------------
__device__ float g_part_kx  [BATCH*NPARTS*CQ*C];
__device__ float g_part_xsum[BATCH*NPARTS*C];
__device__ float g_part_ksum[BATCH*NPARTS*CQ];
__device__ float g_kx  [BATCH*CQ*C];
__device__ float g_xsum[BATCH*C];
__device__ float g_ksum[BATCH*CQ];
__device__ float g_mat [BATCH*CQ*C];
__device__ float g_vsum[BATCH*C];

// ---------------- packed f32x2 helpers ----------------
__device__ __forceinline__ u64 pack2dup(float x) {
    u64 r; asm("mov.b64 %0, {%1, %1};" : "=l"(r) : "f"(x)); return r;
}
__device__ __forceinline__ void unpack2(u64 v, float& lo, float& hi) {
    asm("mov.b64 {%0, %1}, %2;" : "=f"(lo), "=f"(hi) : "l"(v));
}
__device__ __forceinline__ u64 ffma2(u64 a, u64 b, u64 c) {
    u64 d; asm("fma.rn.f32x2 %0, %1, %2, %3;" : "=l"(d) : "l"(a), "l"(b), "l"(c));
    return d;
}
__device__ __forceinline__ u64 fmul2(u64 a, u64 b) {
    u64 d; asm("mul.rn.f32x2 %0, %1, %2;" : "=l"(d) : "l"(a), "l"(b)); return d;
}
__device__ __forceinline__ u64 fadd2(u64 a, u64 b) {
    u64 d; asm("add.rn.f32x2 %0, %1, %2;" : "=l"(d) : "l"(a), "l"(b)); return d;
}

// ---------------- smem layouts (float offsets) ----------------
#define P1_BUF0   0       // x1 [192][64]=12288  OR  xt [64][194]=12416
#define P1_WK     12416   // [32][192]
#define P1_KN     18560   // [32][64]
#define P1_KSQ    20608   // [8][64]
#define P1_INVN   21120   // [64]
#define P1_WKP    21184   // [32]
#define P1_KSUML  21216   // [32]
#define P1_TOT    21248
#define SMEM1_BYTES (P1_TOT*4)

#define P2_XS     0       // [192][64]
#define P2_WQ     12288   // [32][192]
#define P2_MATS   18432   // [32][192]
#define P2_QN     24576   // [32][64]
#define P2_QSQ    26624   // [8][64]
#define P2_INVN   27136
#define P2_SDP    27200   // [8][64]
#define P2_TS     27712
#define P2_KSUM   27776
#define P2_VSUM   27808
#define P2_TOT    28000
#define SMEM2_BYTES (P2_TOT*4)

// =============================================================================
// Pass 1: Kn, KX = Kn·x^T, ksum, xsum (per-block partials)
// =============================================================================
__global__ __launch_bounds__(256, 2)
void pass1_kernel(const float* __restrict__ x, const float* __restrict__ x1,
                  const float* __restrict__ Wk, const float* __restrict__ bk)
{
    extern __shared__ float sm[];
    float* buf0  = sm + P1_BUF0;
    float* wk    = sm + P1_WK;
    float* kn    = sm + P1_KN;
    float* ksq   = sm + P1_KSQ;
    float* invn  = sm + P1_INVN;
    float* wkp   = sm + P1_WKP;
    float* ksuml = sm + P1_KSUML;

    const int tid  = threadIdx.x;
    const int lane = tid & 31;
    const int wgrp = tid >> 5;
    const int b    = blockIdx.y;
    const int part = blockIdx.x;
    const int pl   = 2 * lane;

#pragma unroll
    for (int i = 0; i < 24; i++) wk[tid + i * 256] = Wk[tid + i * 256];
    if (tid < 32) ksuml[tid] = 0.f;

    float bkr[4];
#pragma unroll
    for (int u = 0; u < 4; u++) bkr[u] = bk[wgrp + 8 * u];

    u64 macc[4][3];   // KX: m = wgrp+8i, d-pair = pl + 64j
#pragma unroll
    for (int i = 0; i < 4; i++)
#pragma unroll
        for (int j = 0; j < 3; j++) macc[i][j] = 0ull;
    u64 xacc = 0ull;  // xsum partial (tid<96, ch pair 2*tid)

    const float* x1b = x1 + (size_t)b * C * NPIX;
    const float* xb  = x  + (size_t)b * C * NPIX;

    for (int s = 0; s < NSUBT; s++) {
        const int n0 = part * TILE + s * SUB;
        __syncthreads();   // guard buf0/kn against prev-subtile readers

        // ---- load x1 subtile -> buf0[c][t] ----
#pragma unroll
        for (int i = 0; i < 24; i++) {
            int c = wgrp + 8 * i;
            *(float2*)&buf0[c * 64 + pl] =
                *(const float2*)&x1b[(size_t)c * NPIX + n0 + pl];
        }
        __syncthreads();

        // ---- K projection: 4 m x 2 px, 2 k per weight LDS.64 ----
        u64 acc2[4];
#pragma unroll
        for (int u = 0; u < 4; u++) acc2[u] = pack2dup(bkr[u]);
#pragma unroll 4
        for (int k = 0; k < C; k += 2) {
            u64 xp0 = *(const u64*)&buf0[k * 64 + pl];
            u64 xp1 = *(const u64*)&buf0[(k + 1) * 64 + pl];
#pragma unroll
            for (int u = 0; u < 4; u++) {
                u64 w2 = *(const u64*)&wk[(wgrp + 8 * u) * 192 + k];
                float wl, wh; unpack2(w2, wl, wh);
                acc2[u] = ffma2(xp0, pack2dup(wl), acc2[u]);
                acc2[u] = ffma2(xp1, pack2dup(wh), acc2[u]);
            }
        }
        {
            u64 sq = fmul2(acc2[0], acc2[0]);
#pragma unroll
            for (int u = 1; u < 4; u++) sq = ffma2(acc2[u], acc2[u], sq);
            *(u64*)&ksq[wgrp * 64 + pl] = sq;
        }
        __syncthreads();   // all K-proj buf0 reads done, ksq complete

        if (tid < 64) {
            float tot = 0.f;
#pragma unroll
            for (int g = 0; g < 8; g++) tot += ksq[g * 64 + tid];
            invn[tid] = rsqrtf(tot);
        }
        // ---- load x subtile transposed -> buf0 = xt[t][194] ----
#pragma unroll
        for (int i = 0; i < 24; i++) {
            int c = wgrp + 8 * i;
            float2 v = *(const float2*)&xb[(size_t)c * NPIX + n0 + pl];
            buf0[pl * 194 + c]       = v.x;
            buf0[(pl + 1) * 194 + c] = v.y;
        }
        __syncthreads();   // invn + xt visible

        // ---- kn = K * invn, ksum partials ----
        {
            u64 inv2 = *(const u64*)&invn[pl];
#pragma unroll
            for (int u = 0; u < 4; u++) {
                u64 kp = fmul2(acc2[u], inv2);
                *(u64*)&kn[(wgrp + 8 * u) * 64 + pl] = kp;
                float lo, hi; unpack2(kp, lo, hi);
                float sv = lo + hi;
#pragma unroll
                for (int off = 16; off; off >>= 1)
                    sv += __shfl_down_sync(0xffffffffu, sv, off);
                if (lane == 0) wkp[wgrp * 4 + u] = sv;
            }
        }
        __syncthreads();   // kn + wkp visible
        if (tid < 32) ksuml[tid] += wkp[(tid & 7) * 4 + (tid >> 3)];

        // ---- xsum partial ----
        if (tid < 96) {
            u64 sv = 0ull;
#pragma unroll 8
            for (int t = 0; t < SUB; t++)
                sv = fadd2(sv, *(const u64*)&buf0[t * 194 + 2 * tid]);
            xacc = fadd2(xacc, sv);
        }

        // ---- KX += kn · x^T ----
#pragma unroll 2
        for (int t = 0; t < SUB; t++) {
            u64 kd[4];
#pragma unroll
            for (int i = 0; i < 4; i++)
                kd[i] = pack2dup(kn[(wgrp + 8 * i) * 64 + t]);
#pragma unroll
            for (int j = 0; j < 3; j++) {
                u64 x2 = *(const u64*)&buf0[t * 194 + pl + 64 * j];
#pragma unroll
                for (int i = 0; i < 4; i++)
                    macc[i][j] = ffma2(kd[i], x2, macc[i][j]);
            }
        }
    }

    __syncthreads();
    float* pm = g_part_kx + ((size_t)b * NPARTS + part) * CQ * C;
#pragma unroll
    for (int i = 0; i < 4; i++)
#pragma unroll
        for (int j = 0; j < 3; j++)
            *(u64*)&pm[(wgrp + 8 * i) * C + pl + 64 * j] = macc[i][j];
    if (tid < 96) {
        float lo, hi; unpack2(xacc, lo, hi);
        float* px = g_part_xsum + ((size_t)b * NPARTS + part) * C;
        px[2 * tid] = lo; px[2 * tid + 1] = hi;
    }
    if (tid < 32) g_part_ksum[((size_t)b * NPARTS + part) * CQ + tid] = ksuml[tid];
}

// =============================================================================
// mid1: reduce partials (fixed order => deterministic)
// =============================================================================
__global__ void mid1_kernel()
{
    const int MATN = BATCH * CQ * C;
    const int XSN  = BATCH * C;
    const int KSN  = BATCH * CQ;
    int idx = blockIdx.x * blockDim.x + threadIdx.x;
    if (idx < MATN) {
        int bb = idx / (CQ * C), r = idx % (CQ * C);
        const float* p = g_part_kx + (size_t)bb * NPARTS * CQ * C + r;
        float sv = 0.f;
#pragma unroll 8
        for (int q = 0; q < NPARTS; q++) sv += p[(size_t)q * CQ * C];
        g_kx[idx] = sv;
    } else if (idx < MATN + XSN) {
        int k = idx - MATN;
        int bb = k / C, r = k % C;
        const float* p = g_part_xsum + (size_t)bb * NPARTS * C + r;
        float sv = 0.f;
#pragma unroll 8
        for (int q = 0; q < NPARTS; q++) sv += p[q * C];
        g_xsum[k] = sv;
    } else if (idx < MATN + XSN + KSN) {
        int k = idx - MATN - XSN;
        int bb = k / CQ, r = k % CQ;
        const float* p = g_part_ksum + (size_t)bb * NPARTS * CQ + r;
        float sv = 0.f;
#pragma unroll 8
        for (int q = 0; q < NPARTS; q++) sv += p[q * CQ];
        g_ksum[k] = sv;
    }
}

// =============================================================================
// mid2: matrix = KX·Wv^T + ksum·bv^T ; vsum = Wv·xsum + N·bv
// grid 64: b = blk>>3, c-range = (blk&7)*24
// =============================================================================
__global__ __launch_bounds__(256)
void mid2_kernel(const float* __restrict__ Wv, const float* __restrict__ bv)
{
    __shared__ float kxs[32 * 193];
    __shared__ float wvs[24 * 193];
    __shared__ float xsum_s[192];
    __shared__ float ksum_s[32];
    const int tid = threadIdx.x;
    const int b = blockIdx.x >> 3;
    const int c0 = (blockIdx.x & 7) * 24;

#pragma unroll
    for (int i = 0; i < 24; i++) {
        int idx = tid + 256 * i;
        int m = idx / 192, d = idx - m * 192;
        kxs[m * 193 + d] = g_kx[b * (CQ * C) + idx];
    }
#pragma unroll
    for (int i = 0; i < 18; i++) {
        int idx = tid + 256 * i;
        int r = idx / 192, d = idx - r * 192;
        wvs[r * 193 + d] = Wv[(size_t)(c0 + r) * C + d];
    }
    if (tid < 192) xsum_s[tid] = g_xsum[b * C + tid];
    if (tid < 32)  ksum_s[tid] = g_ksum[b * CQ + tid];
    __syncthreads();

#pragma unroll
    for (int e = 0; e < 3; e++) {
        int o = tid + 256 * e;          // < 768 = 32 m x 24 c
        int m = o / 24, c = o - m * 24;
        float acc = ksum_s[m] * bv[c0 + c];
#pragma unroll 8
        for (int d = 0; d < 192; d++)
            acc = fmaf(kxs[m * 193 + d], wvs[c * 193 + d], acc);
        g_mat[b * (CQ * C) + m * C + c0 + c] = acc;
    }
    if (tid < 24) {
        float acc = (float)NPIX * bv[c0 + tid];
#pragma unroll 8
        for (int d = 0; d < 192; d++)
            acc = fmaf(wvs[tid * 193 + d], xsum_s[d], acc);
        g_vsum[b * C + c0 + tid] = acc;
    }
}

// =============================================================================
// Pass 2: Qn, tailor_sum, out = gamma*ts*(vsum + Qn·matrix)
// =============================================================================
__global__ __launch_bounds__(256, 2)
void pass2_kernel(const float* __restrict__ x1,
                  const float* __restrict__ Wq, const float* __restrict__ bq,
                  const float* __restrict__ gamma, float* __restrict__ out)
{
    extern __shared__ float sm[];
    float* xs     = sm + P2_XS;
    float* wq     = sm + P2_WQ;
    float* mats   = sm + P2_MATS;
    float* qn     = sm + P2_QN;
    float* qsq    = sm + P2_QSQ;
    float* invn   = sm + P2_INVN;
    float* sdp    = sm + P2_SDP;
    float* ts_s   = sm + P2_TS;
    float* ksum_s = sm + P2_KSUM;
    float* vsum_s = sm + P2_VSUM;

    const int tid  = threadIdx.x;
    const int lane = tid & 31;
    const int wgrp = tid >> 5;
    const int b    = blockIdx.y;
    const int part = blockIdx.x;
    const int pl   = 2 * lane;
    const int c0   = wgrp * 24;
    const float gm = gamma[0];

#pragma unroll
    for (int i = 0; i < 24; i++) {
        wq[tid + i * 256]   = Wq[tid + i * 256];
        mats[tid + i * 256] = g_mat[(size_t)b * CQ * C + tid + i * 256];
    }
    if (tid < 32)  ksum_s[tid] = g_ksum[b * CQ + tid] + 1e-6f;
    if (tid < 192) vsum_s[tid] = g_vsum[b * C + tid];

    float bqr[4];
#pragma unroll
    for (int u = 0; u < 4; u++) bqr[u] = bq[wgrp + 8 * u];

    const float* x1b = x1 + (size_t)b * C * NPIX;
    float* outb = out + (size_t)b * C * NPIX;

    for (int s = 0; s < NSUBT; s++) {
        const int n0 = part * TILE + s * SUB;
        __syncthreads();
#pragma unroll
        for (int i = 0; i < 24; i++) {
            int c = wgrp + 8 * i;
            *(float2*)&xs[c * 64 + pl] =
                *(const float2*)&x1b[(size_t)c * NPIX + n0 + pl];
        }
        __syncthreads();

        // ---- Q projection (2 k per weight LDS.64) ----
        u64 acc2[4];
#pragma unroll
        for (int u = 0; u < 4; u++) acc2[u] = pack2dup(bqr[u]);
#pragma unroll 4
        for (int k = 0; k < C; k += 2) {
            u64 xp0 = *(const u64*)&xs[k * 64 + pl];
            u64 xp1 = *(const u64*)&xs[(k + 1) * 64 + pl];
#pragma unroll
            for (int u = 0; u < 4; u++) {
                u64 w2 = *(const u64*)&wq[(wgrp + 8 * u) * 192 + k];
                float wl, wh; unpack2(w2, wl, wh);
                acc2[u] = ffma2(xp0, pack2dup(wl), acc2[u]);
                acc2[u] = ffma2(xp1, pack2dup(wh), acc2[u]);
            }
        }
        {
            u64 sq = fmul2(acc2[0], acc2[0]);
#pragma unroll
            for (int u = 1; u < 4; u++) sq = ffma2(acc2[u], acc2[u], sq);
            *(u64*)&qsq[wgrp * 64 + pl] = sq;
        }
        __syncthreads();
        if (tid < 64) {
            float tot = 0.f;
#pragma unroll
            for (int g = 0; g < 8; g++) tot += qsq[g * 64 + tid];
            invn[tid] = rsqrtf(tot);
        }
        __syncthreads();
        {
            u64 inv2 = *(const u64*)&invn[pl];
            u64 sd2 = 0ull;
#pragma unroll
            for (int u = 0; u < 4; u++) {
                u64 qp = fmul2(acc2[u], inv2);
                *(u64*)&qn[(wgrp + 8 * u) * 64 + pl] = qp;
                sd2 = ffma2(qp, pack2dup(ksum_s[wgrp + 8 * u]), sd2);
            }
            *(u64*)&sdp[wgrp * 64 + pl] = sd2;
        }
        __syncthreads();
        if (tid < 64) {
            float tot = 0.f;
#pragma unroll
            for (int g = 0; g < 8; g++) tot += sdp[g * 64 + tid];
            ts_s[tid] = 1.0f / ((float)NPIX + tot);
        }
        __syncthreads();

        // ---- out GEMM: 2 px x 12 ch-pairs per thread ----
        u64 oacc[2][12];
#pragma unroll
        for (int j = 0; j < 12; j++) {
            u64 vp = *(const u64*)&vsum_s[c0 + 2 * j];
            oacc[0][j] = vp; oacc[1][j] = vp;
        }
#pragma unroll 4
        for (int m = 0; m < CQ; m++) {
            float2 qq = *(const float2*)&qn[m * 64 + pl];
            u64 q0 = pack2dup(qq.x);
            u64 q1 = pack2dup(qq.y);
#pragma unroll
            for (int j = 0; j < 12; j++) {
                u64 w2 = *(const u64*)&mats[m * C + c0 + 2 * j];
                oacc[0][j] = ffma2(w2, q0, oacc[0][j]);
                oacc[1][j] = ffma2(w2, q1, oacc[1][j]);
            }
        }
        {
            float2 tss = *(const float2*)&ts_s[pl];
            u64 g0 = pack2dup(gm * tss.x);
            u64 g1 = pack2dup(gm * tss.y);
#pragma unroll
            for (int j = 0; j < 12; j++) {
                u64 o0 = fmul2(oacc[0][j], g0);
                u64 o1 = fmul2(oacc[1][j], g1);
                float a0, a1, b0, b1;
                unpack2(o0, a0, a1);
                unpack2(o1, b0, b1);
                *(float2*)&outb[(size_t)(c0 + 2 * j)     * NPIX + n0 + pl] =
                    make_float2(a0, b0);
                *(float2*)&outb[(size_t)(c0 + 2 * j + 1) * NPIX + n0 + pl] =
                    make_float2(a1, b1);
            }
        }
    }
}

// =============================================================================
extern "C" void kernel_launch(void* const* d_in, const int* in_sizes, int n_in,
                              void* d_out, int out_size)
{
    const float* x     = (const float*)d_in[0];
    const float* x1    = (const float*)d_in[1];
    const float* Wq    = (const float*)d_in[2];
    const float* bq    = (const float*)d_in[3];
    const float* Wk    = (const float*)d_in[4];
    const float* bk    = (const float*)d_in[5];
    const float* Wv    = (const float*)d_in[6];
    const float* bv    = (const float*)d_in[7];
    const float* gamma = (const float*)d_in[8];
    float* out = (float*)d_out;

    cudaFuncSetAttribute(pass1_kernel,
                         cudaFuncAttributeMaxDynamicSharedMemorySize, SMEM1_BYTES);
    cudaFuncSetAttribute(pass2_kernel,
                         cudaFuncAttributeMaxDynamicSharedMemorySize, SMEM2_BYTES);

    dim3 grid(NPARTS, BATCH);
    pass1_kernel<<<grid, 256, SMEM1_BYTES>>>(x, x1, Wk, bk);

    const int RED = BATCH * CQ * C + BATCH * C + BATCH * CQ;
    mid1_kernel<<<(RED + 255) / 256, 256>>>();
    mid2_kernel<<<64, 256>>>(Wv, bv);

    pass2_kernel<<<grid, 256, SMEM2_BYTES>>>(x1, Wq, bq, gamma, out);
}

// round 5
// speedup vs baseline: 2.2499x; 1.0071x over previous
#include <cuda_runtime.h>
#include <cstdint>

#define BATCH 8
#define C     192
#define CQ    32
#define NPIX  16384
#define SUB   64
#define NSUBT 4
#define TILE  (SUB*NSUBT)
#define NPARTS (NPIX/TILE)   // 64

typedef unsigned long long u64;

// ---------------- deterministic scratch ----------------
__device__ float g_part_kx  [BATCH*NPARTS*CQ*C];
__device__ float g_part_xsum[BATCH*NPARTS*C];
__device__ float g_part_ksum[BATCH*NPARTS*CQ];
__device__ float g_kx  [BATCH*CQ*C];
__device__ float g_xsum[BATCH*C];
__device__ float g_ksum[BATCH*CQ];
__device__ float g_mat [BATCH*CQ*C];
__device__ float g_vsum[BATCH*C];

// ---------------- packed f32x2 helpers ----------------
__device__ __forceinline__ u64 pack2dup(float x) {
    u64 r; asm("mov.b64 %0, {%1, %1};" : "=l"(r) : "f"(x)); return r;
}
__device__ __forceinline__ u64 pack2(float a, float b) {
    u64 r; asm("mov.b64 %0, {%1, %2};" : "=l"(r) : "f"(a), "f"(b)); return r;
}
__device__ __forceinline__ void unpack2(u64 v, float& lo, float& hi) {
    asm("mov.b64 {%0, %1}, %2;" : "=f"(lo), "=f"(hi) : "l"(v));
}
__device__ __forceinline__ u64 ffma2(u64 a, u64 b, u64 c) {
    u64 d; asm("fma.rn.f32x2 %0, %1, %2, %3;" : "=l"(d) : "l"(a), "l"(b), "l"(c));
    return d;
}
__device__ __forceinline__ u64 fmul2(u64 a, u64 b) {
    u64 d; asm("mul.rn.f32x2 %0, %1, %2;" : "=l"(d) : "l"(a), "l"(b)); return d;
}
__device__ __forceinline__ u64 fadd2(u64 a, u64 b) {
    u64 d; asm("add.rn.f32x2 %0, %1, %2;" : "=l"(d) : "l"(a), "l"(b)); return d;
}

// ---------------- smem layouts (float offsets) ----------------
#define P1_BUF0   0        // x1 [192][64]=12288  OR  xt [64][194]=12416
#define P1_WK     12416    // [32][194]
#define P1_KN     18624    // [32][64]
#define P1_KSQ    20672    // [8][64]
#define P1_INVN   21184
#define P1_WKP    21248
#define P1_KSUML  21280
#define P1_TOT    21312
#define SMEM1_BYTES (P1_TOT*4)

#define P2_XS     0        // [192][64]
#define P2_WQ     12288    // [32][194]
#define P2_MATS   18496    // [32][192]
#define P2_QN     24640    // [32][64]
#define P2_QSQ    26688    // [8][64]
#define P2_INVN   27200
#define P2_SDP    27264    // [8][64]
#define P2_TS     27776
#define P2_KSUM   27840
#define P2_VSUM   27872
#define P2_TOT    28064
#define SMEM2_BYTES (P2_TOT*4)

// =============================================================================
// Pass 1: Kn, KX = Kn·x^T, ksum, xsum (per-block partials)
// proj threads (tid<128): mg = tid>>4, pp = tid&15, px quad = 4*pp, m = mg*4+mi
// =============================================================================
__global__ __launch_bounds__(256, 2)
void pass1_kernel(const float* __restrict__ x, const float* __restrict__ x1,
                  const float* __restrict__ Wk, const float* __restrict__ bk)
{
    extern __shared__ float sm[];
    float* buf0  = sm + P1_BUF0;
    float* wk    = sm + P1_WK;
    float* kn    = sm + P1_KN;
    float* ksq   = sm + P1_KSQ;
    float* invn  = sm + P1_INVN;
    float* wkp   = sm + P1_WKP;
    float* ksuml = sm + P1_KSUML;

    const int tid  = threadIdx.x;
    const int lane = tid & 31;
    const int wgrp = tid >> 5;
    const int b    = blockIdx.y;
    const int part = blockIdx.x;
    const int pl   = 2 * lane;
    const int mg   = tid >> 4;     // valid for tid<128
    const int pp   = tid & 15;
    const int qd   = 4 * pp;

    // stage Wk [m][k] stride 194
#pragma unroll
    for (int i = 0; i < 24; i++) {
        int idx = tid + 256 * i;
        int m = idx / 192, k = idx - m * 192;
        wk[m * 194 + k] = Wk[idx];
    }
    if (tid < 32) ksuml[tid] = 0.f;

    float bkr[4];
    if (tid < 128) {
#pragma unroll
        for (int mi = 0; mi < 4; mi++) bkr[mi] = bk[mg * 4 + mi];
    }

    u64 macc[4][3];   // KX: m = wgrp+8i, d-pair = pl + 64j
#pragma unroll
    for (int i = 0; i < 4; i++)
#pragma unroll
        for (int j = 0; j < 3; j++) macc[i][j] = 0ull;
    u64 xacc = 0ull;  // xsum partial (tid in [128,224), ch-pair 2*(tid-128))

    const float* x1b = x1 + (size_t)b * C * NPIX;
    const float* xb  = x  + (size_t)b * C * NPIX;

    for (int s = 0; s < NSUBT; s++) {
        const int n0 = part * TILE + s * SUB;
        __syncthreads();   // A: buf0/kn reuse guard

        // ---- stage x1 -> buf0[c][t], float4 ----
#pragma unroll
        for (int i = 0; i < 12; i++) {
            int idx = tid + 256 * i;
            int c = idx >> 4, q = idx & 15;
            *(float4*)&buf0[c * 64 + 4 * q] =
                *(const float4*)&x1b[(size_t)c * NPIX + n0 + 4 * q];
        }
        __syncthreads();   // B

        u64 acc[4][2];
        float2 xr[24];
        if (tid < 128) {
            // ---- K projection: 4 px quad x 4 m ----
#pragma unroll
            for (int mi = 0; mi < 4; mi++) {
                u64 bb2 = pack2dup(bkr[mi]);
                acc[mi][0] = bb2; acc[mi][1] = bb2;
            }
#pragma unroll 6
            for (int k = 0; k < C; k += 2) {
                float4 xa = *(const float4*)&buf0[k * 64 + qd];
                float4 xc = *(const float4*)&buf0[(k + 1) * 64 + qd];
                u64 xa0 = pack2(xa.x, xa.y), xa1 = pack2(xa.z, xa.w);
                u64 xc0 = pack2(xc.x, xc.y), xc1 = pack2(xc.z, xc.w);
#pragma unroll
                for (int mi = 0; mi < 4; mi++) {
                    u64 w2 = *(const u64*)&wk[(mg * 4 + mi) * 194 + k];
                    float wl, wh; unpack2(w2, wl, wh);
                    u64 wld = pack2dup(wl), whd = pack2dup(wh);
                    acc[mi][0] = ffma2(xa0, wld, acc[mi][0]);
                    acc[mi][1] = ffma2(xa1, wld, acc[mi][1]);
                    acc[mi][0] = ffma2(xc0, whd, acc[mi][0]);
                    acc[mi][1] = ffma2(xc1, whd, acc[mi][1]);
                }
            }
            u64 sq0 = fmul2(acc[0][0], acc[0][0]);
            u64 sq1 = fmul2(acc[0][1], acc[0][1]);
#pragma unroll
            for (int mi = 1; mi < 4; mi++) {
                sq0 = ffma2(acc[mi][0], acc[mi][0], sq0);
                sq1 = ffma2(acc[mi][1], acc[mi][1], sq1);
            }
            *(u64*)&ksq[mg * 64 + qd]     = sq0;
            *(u64*)&ksq[mg * 64 + qd + 2] = sq1;
        } else {
            // ---- prefetch x lower-channel half into regs ----
            const int u = tid - 128;
            const int plu = 2 * (u & 31);
#pragma unroll
            for (int i = 0; i < 24; i++) {
                int c = (u >> 5) + 4 * i;     // 0..95
                xr[i] = *(const float2*)&xb[(size_t)c * NPIX + n0 + plu];
            }
        }
        __syncthreads();   // C: ksq complete, buf0(x1) reads done

        if (tid < 64) {
            float tot = 0.f;
#pragma unroll
            for (int g = 0; g < 8; g++) tot += ksq[g * 64 + tid];
            invn[tid] = rsqrtf(tot);
        }
        if (tid >= 128) {
            const int u = tid - 128;
            const int plu = 2 * (u & 31);
#pragma unroll
            for (int i = 0; i < 24; i++) {
                int c = (u >> 5) + 4 * i;
                buf0[plu * 194 + c]       = xr[i].x;
                buf0[(plu + 1) * 194 + c] = xr[i].y;
            }
        } else {
#pragma unroll
            for (int i = 0; i < 24; i++) {
                int c = 96 + (tid >> 5) + 4 * i;   // 96..191
                float2 v = *(const float2*)&xb[(size_t)c * NPIX + n0 + pl];
                buf0[pl * 194 + c]       = v.x;
                buf0[(pl + 1) * 194 + c] = v.y;
            }
        }
        __syncthreads();   // D: invn + xt complete

        if (tid < 128) {
            // ---- kn = K*invn, ksum partials ----
            float4 iv = *(const float4*)&invn[qd];
            u64 iv0 = pack2(iv.x, iv.y), iv1 = pack2(iv.z, iv.w);
            float ksump[4];
#pragma unroll
            for (int mi = 0; mi < 4; mi++) {
                u64 k0 = fmul2(acc[mi][0], iv0);
                u64 k1 = fmul2(acc[mi][1], iv1);
                float a0, a1, a2, a3;
                unpack2(k0, a0, a1); unpack2(k1, a2, a3);
                *(float4*)&kn[(mg * 4 + mi) * 64 + qd] =
                    make_float4(a0, a1, a2, a3);
                ksump[mi] = (a0 + a1) + (a2 + a3);
            }
#pragma unroll
            for (int off = 8; off; off >>= 1)
#pragma unroll
                for (int mi = 0; mi < 4; mi++)
                    ksump[mi] += __shfl_down_sync(0xffffffffu, ksump[mi], off, 16);
            if (pp == 0)
#pragma unroll
                for (int mi = 0; mi < 4; mi++) wkp[mg * 4 + mi] = ksump[mi];
        } else if (tid < 224) {
            // ---- xsum over xt ----
            const int idx = tid - 128;   // 0..95
            u64 sv = 0ull;
#pragma unroll 8
            for (int t = 0; t < SUB; t++)
                sv = fadd2(sv, *(const u64*)&buf0[t * 194 + 2 * idx]);
            xacc = fadd2(xacc, sv);
        }
        __syncthreads();   // E: kn + wkp complete

        if (tid < 32) ksuml[tid] += wkp[tid];

        // ---- KX += kn · x^T  (t-block-4, broadcast kn LDS.128) ----
#pragma unroll 4
        for (int tb = 0; tb < 16; tb++) {
            const int t0 = 4 * tb;
            float4 kd[4];
#pragma unroll
            for (int i = 0; i < 4; i++)
                kd[i] = *(const float4*)&kn[(wgrp + 8 * i) * 64 + t0];
#pragma unroll
            for (int tt = 0; tt < 4; tt++) {
                u64 x2[3];
#pragma unroll
                for (int j = 0; j < 3; j++)
                    x2[j] = *(const u64*)&buf0[(t0 + tt) * 194 + pl + 64 * j];
                const float* kf0 = (const float*)&kd[0];
                const float* kf1 = (const float*)&kd[1];
                const float* kf2 = (const float*)&kd[2];
                const float* kf3 = (const float*)&kd[3];
                u64 kd0 = pack2dup(kf0[tt]);
                u64 kd1 = pack2dup(kf1[tt]);
                u64 kd2 = pack2dup(kf2[tt]);
                u64 kd3 = pack2dup(kf3[tt]);
#pragma unroll
                for (int j = 0; j < 3; j++) {
                    macc[0][j] = ffma2(kd0, x2[j], macc[0][j]);
                    macc[1][j] = ffma2(kd1, x2[j], macc[1][j]);
                    macc[2][j] = ffma2(kd2, x2[j], macc[2][j]);
                    macc[3][j] = ffma2(kd3, x2[j], macc[3][j]);
                }
            }
        }
    }

    __syncthreads();
    float* pm = g_part_kx + ((size_t)b * NPARTS + part) * CQ * C;
#pragma unroll
    for (int i = 0; i < 4; i++)
#pragma unroll
        for (int j = 0; j < 3; j++)
            *(u64*)&pm[(wgrp + 8 * i) * C + pl + 64 * j] = macc[i][j];
    if (tid >= 128 && tid < 224) {
        const int idx = tid - 128;
        float lo, hi; unpack2(xacc, lo, hi);
        float* px = g_part_xsum + ((size_t)b * NPARTS + part) * C;
        px[2 * idx] = lo; px[2 * idx + 1] = hi;
    }
    if (tid < 32) g_part_ksum[((size_t)b * NPARTS + part) * CQ + tid] = ksuml[tid];
}

// =============================================================================
// mid1: reduce partials (fixed order, float4)
// =============================================================================
__global__ void mid1_kernel()
{
    const int MAT4 = BATCH * CQ * C / 4;   // 12288
    const int XS4  = BATCH * C / 4;        // 384
    const int KS4  = BATCH * CQ / 4;       // 64
    int idx = blockIdx.x * blockDim.x + threadIdx.x;
    if (idx < MAT4) {
        int i4 = idx * 4;
        int bb = i4 / (CQ * C), r = i4 % (CQ * C);
        const float* p = g_part_kx + (size_t)bb * NPARTS * CQ * C + r;
        float4 a = make_float4(0.f, 0.f, 0.f, 0.f);
#pragma unroll 8
        for (int q = 0; q < NPARTS; q++) {
            float4 v = *(const float4*)&p[(size_t)q * CQ * C];
            a.x += v.x; a.y += v.y; a.z += v.z; a.w += v.w;
        }
        *(float4*)&g_kx[i4] = a;
    } else if (idx < MAT4 + XS4) {
        int i4 = (idx - MAT4) * 4;
        int bb = i4 / C, r = i4 % C;
        const float* p = g_part_xsum + (size_t)bb * NPARTS * C + r;
        float4 a = make_float4(0.f, 0.f, 0.f, 0.f);
#pragma unroll 8
        for (int q = 0; q < NPARTS; q++) {
            float4 v = *(const float4*)&p[q * C];
            a.x += v.x; a.y += v.y; a.z += v.z; a.w += v.w;
        }
        *(float4*)&g_xsum[i4] = a;
    } else if (idx < MAT4 + XS4 + KS4) {
        int i4 = (idx - MAT4 - XS4) * 4;
        int bb = i4 / CQ, r = i4 % CQ;
        const float* p = g_part_ksum + (size_t)bb * NPARTS * CQ + r;
        float4 a = make_float4(0.f, 0.f, 0.f, 0.f);
#pragma unroll 8
        for (int q = 0; q < NPARTS; q++) {
            float4 v = *(const float4*)&p[q * CQ];
            a.x += v.x; a.y += v.y; a.z += v.z; a.w += v.w;
        }
        *(float4*)&g_ksum[i4] = a;
    }
}

// =============================================================================
// mid2: matrix = KX·Wv^T + ksum·bv^T ; vsum = Wv·xsum + N·bv
// =============================================================================
__global__ __launch_bounds__(256)
void mid2_kernel(const float* __restrict__ Wv, const float* __restrict__ bv)
{
    __shared__ float kxs[32 * 193];
    __shared__ float wvs[24 * 193];
    __shared__ float xsum_s[192];
    __shared__ float ksum_s[32];
    const int tid = threadIdx.x;
    const int b = blockIdx.x >> 3;
    const int c0 = (blockIdx.x & 7) * 24;

#pragma unroll
    for (int i = 0; i < 24; i++) {
        int idx = tid + 256 * i;
        int m = idx / 192, d = idx - m * 192;
        kxs[m * 193 + d] = g_kx[b * (CQ * C) + idx];
    }
#pragma unroll
    for (int i = 0; i < 18; i++) {
        int idx = tid + 256 * i;
        int r = idx / 192, d = idx - r * 192;
        wvs[r * 193 + d] = Wv[(size_t)(c0 + r) * C + d];
    }
    if (tid < 192) xsum_s[tid] = g_xsum[b * C + tid];
    if (tid < 32)  ksum_s[tid] = g_ksum[b * CQ + tid];
    __syncthreads();

#pragma unroll
    for (int e = 0; e < 3; e++) {
        int o = tid + 256 * e;
        int m = o / 24, c = o - m * 24;
        float acc = ksum_s[m] * bv[c0 + c];
#pragma unroll 8
        for (int d = 0; d < 192; d++)
            acc = fmaf(kxs[m * 193 + d], wvs[c * 193 + d], acc);
        g_mat[b * (CQ * C) + m * C + c0 + c] = acc;
    }
    if (tid < 24) {
        float acc = (float)NPIX * bv[c0 + tid];
#pragma unroll 8
        for (int d = 0; d < 192; d++)
            acc = fmaf(wvs[tid * 193 + d], xsum_s[d], acc);
        g_vsum[b * C + c0 + tid] = acc;
    }
}

// =============================================================================
// Pass 2: Qn, tailor_sum, out = gamma*ts*(vsum + Qn·matrix)
// =============================================================================
__global__ __launch_bounds__(256, 2)
void pass2_kernel(const float* __restrict__ x1,
                  const float* __restrict__ Wq, const float* __restrict__ bq,
                  const float* __restrict__ gamma, float* __restrict__ out)
{
    extern __shared__ float sm[];
    float* xs     = sm + P2_XS;
    float* wq     = sm + P2_WQ;
    float* mats   = sm + P2_MATS;
    float* qn     = sm + P2_QN;
    float* qsq    = sm + P2_QSQ;
    float* invn   = sm + P2_INVN;
    float* sdp    = sm + P2_SDP;
    float* ts_s   = sm + P2_TS;
    float* ksum_s = sm + P2_KSUM;
    float* vsum_s = sm + P2_VSUM;

    const int tid  = threadIdx.x;
    const int b    = blockIdx.y;
    const int part = blockIdx.x;
    const int mg   = tid >> 4;      // proj (tid<128)
    const int pp   = tid & 15;
    const int qd   = 4 * pp;
    const int cg   = tid >> 4;      // out-GEMM ch-group (reuse)
    const float gm = gamma[0];

#pragma unroll
    for (int i = 0; i < 24; i++) {
        int idx = tid + 256 * i;
        int m = idx / 192, k = idx - m * 192;
        wq[m * 194 + k]  = Wq[idx];
        mats[idx] = g_mat[(size_t)b * CQ * C + idx];
    }
    if (tid < 32)  ksum_s[tid] = g_ksum[b * CQ + tid] + 1e-6f;
    if (tid < 192) vsum_s[tid] = g_vsum[b * C + tid];

    float bqr[4];
    if (tid < 128) {
#pragma unroll
        for (int mi = 0; mi < 4; mi++) bqr[mi] = bq[mg * 4 + mi];
    }

    const float* x1b = x1 + (size_t)b * C * NPIX;
    float* outb = out + (size_t)b * C * NPIX;

    for (int s = 0; s < NSUBT; s++) {
        const int n0 = part * TILE + s * SUB;
        __syncthreads();   // A
        if (s == 0 || tid < 128) {
#pragma unroll
            for (int i = 0; i < 12; i++) {
                int idx = tid + 256 * i;
                int c = idx >> 4, q = idx & 15;
                *(float4*)&xs[c * 64 + 4 * q] =
                    *(const float4*)&x1b[(size_t)c * NPIX + n0 + 4 * q];
            }
        }
        __syncthreads();   // B

        u64 acc[4][2];
        float4 xr4[12];
        if (tid < 128) {
            // ---- Q projection ----
#pragma unroll
            for (int mi = 0; mi < 4; mi++) {
                u64 bb2 = pack2dup(bqr[mi]);
                acc[mi][0] = bb2; acc[mi][1] = bb2;
            }
#pragma unroll 6
            for (int k = 0; k < C; k += 2) {
                float4 xa = *(const float4*)&xs[k * 64 + qd];
                float4 xc = *(const float4*)&xs[(k + 1) * 64 + qd];
                u64 xa0 = pack2(xa.x, xa.y), xa1 = pack2(xa.z, xa.w);
                u64 xc0 = pack2(xc.x, xc.y), xc1 = pack2(xc.z, xc.w);
#pragma unroll
                for (int mi = 0; mi < 4; mi++) {
                    u64 w2 = *(const u64*)&wq[(mg * 4 + mi) * 194 + k];
                    float wl, wh; unpack2(w2, wl, wh);
                    u64 wld = pack2dup(wl), whd = pack2dup(wh);
                    acc[mi][0] = ffma2(xa0, wld, acc[mi][0]);
                    acc[mi][1] = ffma2(xa1, wld, acc[mi][1]);
                    acc[mi][0] = ffma2(xc0, whd, acc[mi][0]);
                    acc[mi][1] = ffma2(xc1, whd, acc[mi][1]);
                }
            }
            u64 sq0 = fmul2(acc[0][0], acc[0][0]);
            u64 sq1 = fmul2(acc[0][1], acc[0][1]);
#pragma unroll
            for (int mi = 1; mi < 4; mi++) {
                sq0 = ffma2(acc[mi][0], acc[mi][0], sq0);
                sq1 = ffma2(acc[mi][1], acc[mi][1], sq1);
            }
            *(u64*)&qsq[mg * 64 + qd]     = sq0;
            *(u64*)&qsq[mg * 64 + qd + 2] = sq1;
        } else if (s < 3) {
            // ---- prefetch next subtile x1 (upper half of staging set) ----
            const int n1 = n0 + SUB;
#pragma unroll
            for (int i = 0; i < 12; i++) {
                int idx = tid + 256 * i;
                int c = idx >> 4, q = idx & 15;
                xr4[i] = *(const float4*)&x1b[(size_t)c * NPIX + n1 + 4 * q];
            }
        }
        __syncthreads();   // C
        if (tid < 64) {
            float tot = 0.f;
#pragma unroll
            for (int g = 0; g < 8; g++) tot += qsq[g * 64 + tid];
            invn[tid] = rsqrtf(tot);
        }
        __syncthreads();   // D
        if (tid < 128) {
            float4 iv = *(const float4*)&invn[qd];
            u64 iv0 = pack2(iv.x, iv.y), iv1 = pack2(iv.z, iv.w);
            u64 sd0 = 0ull, sd1 = 0ull;
#pragma unroll
            for (int mi = 0; mi < 4; mi++) {
                u64 q0 = fmul2(acc[mi][0], iv0);
                u64 q1 = fmul2(acc[mi][1], iv1);
                float a0, a1, a2, a3;
                unpack2(q0, a0, a1); unpack2(q1, a2, a3);
                *(float4*)&qn[(mg * 4 + mi) * 64 + qd] =
                    make_float4(a0, a1, a2, a3);
                u64 ks = pack2dup(ksum_s[mg * 4 + mi]);
                sd0 = ffma2(q0, ks, sd0);
                sd1 = ffma2(q1, ks, sd1);
            }
            *(u64*)&sdp[mg * 64 + qd]     = sd0;
            *(u64*)&sdp[mg * 64 + qd + 2] = sd1;
        }
        __syncthreads();   // E
        if (tid < 64) {
            float tot = 0.f;
#pragma unroll
            for (int g = 0; g < 8; g++) tot += sdp[g * 64 + tid];
            ts_s[tid] = 1.0f / ((float)NPIX + tot);
        }
        __syncthreads();   // F
        if (tid >= 128 && s < 3) {
#pragma unroll
            for (int i = 0; i < 12; i++) {
                int idx = tid + 256 * i;
                int c = idx >> 4, q = idx & 15;
                *(float4*)&xs[c * 64 + 4 * q] = xr4[i];
            }
        }

        // ---- out GEMM: px quad 4*pp x 12 ch (cg*12) ----
        u64 oacc[4][6];
#pragma unroll
        for (int e = 0; e < 6; e++) {
            u64 vp = *(const u64*)&vsum_s[cg * 12 + 2 * e];
            oacc[0][e] = vp; oacc[1][e] = vp; oacc[2][e] = vp; oacc[3][e] = vp;
        }
#pragma unroll 4
        for (int m = 0; m < CQ; m++) {
            float4 qv = *(const float4*)&qn[m * 64 + qd];
            u64 q0 = pack2dup(qv.x), q1 = pack2dup(qv.y);
            u64 q2 = pack2dup(qv.z), q3 = pack2dup(qv.w);
#pragma unroll
            for (int e = 0; e < 6; e++) {
                u64 w2 = *(const u64*)&mats[m * 192 + cg * 12 + 2 * e];
                oacc[0][e] = ffma2(w2, q0, oacc[0][e]);
                oacc[1][e] = ffma2(w2, q1, oacc[1][e]);
                oacc[2][e] = ffma2(w2, q2, oacc[2][e]);
                oacc[3][e] = ffma2(w2, q3, oacc[3][e]);
            }
        }
        {
            float4 tv = *(const float4*)&ts_s[qd];
            u64 g0 = pack2dup(gm * tv.x), g1 = pack2dup(gm * tv.y);
            u64 g2 = pack2dup(gm * tv.z), g3 = pack2dup(gm * tv.w);
#pragma unroll
            for (int e = 0; e < 6; e++) {
                u64 o0 = fmul2(oacc[0][e], g0);
                u64 o1 = fmul2(oacc[1][e], g1);
                u64 o2 = fmul2(oacc[2][e], g2);
                u64 o3 = fmul2(oacc[3][e], g3);
                float l0, h0, l1, h1, l2, h2, l3, h3;
                unpack2(o0, l0, h0); unpack2(o1, l1, h1);
                unpack2(o2, l2, h2); unpack2(o3, l3, h3);
                const int c = cg * 12 + 2 * e;
                *(float4*)&outb[(size_t)c * NPIX + n0 + qd] =
                    make_float4(l0, l1, l2, l3);
                *(float4*)&outb[(size_t)(c + 1) * NPIX + n0 + qd] =
                    make_float4(h0, h1, h2, h3);
            }
        }
    }
}

// =============================================================================
extern "C" void kernel_launch(void* const* d_in, const int* in_sizes, int n_in,
                              void* d_out, int out_size)
{
    const float* x     = (const float*)d_in[0];
    const float* x1    = (const float*)d_in[1];
    const float* Wq    = (const float*)d_in[2];
    const float* bq    = (const float*)d_in[3];
    const float* Wk    = (const float*)d_in[4];
    const float* bk    = (const float*)d_in[5];
    const float* Wv    = (const float*)d_in[6];
    const float* bv    = (const float*)d_in[7];
    const float* gamma = (const float*)d_in[8];
    float* out = (float*)d_out;

    cudaFuncSetAttribute(pass1_kernel,
                         cudaFuncAttributeMaxDynamicSharedMemorySize, SMEM1_BYTES);
    cudaFuncSetAttribute(pass2_kernel,
                         cudaFuncAttributeMaxDynamicSharedMemorySize, SMEM2_BYTES);

    dim3 grid(NPARTS, BATCH);
    pass1_kernel<<<grid, 256, SMEM1_BYTES>>>(x, x1, Wk, bk);

    const int R4 = BATCH * CQ * C / 4 + BATCH * C / 4 + BATCH * CQ / 4;
    mid1_kernel<<<(R4 + 255) / 256, 256>>>();
    mid2_kernel<<<64, 256>>>(Wv, bv);

    pass2_kernel<<<grid, 256, SMEM2_BYTES>>>(x1, Wq, bq, gamma, out);
}